// round 7
// baseline (speedup 1.0000x reference)
#include <cuda_runtime.h>
#include <math.h>
#include <stdint.h>

#define Bn 128
#define Tn 1024
#define Hn 512

// Packed dual-FMA: acc(f32x2) += a(f32x2) * b(f32x2), IEEE fp32 per lane.
#define FMA2(acc, a, b) \
    asm("fma.rn.f32x2 %0, %1, %2, %0;" : "+l"(acc) : "l"(a), "l"(b))

union UF2 { unsigned long long u; float2 f; };

// Per-(rowgroup, step) arrival counters + packed weights (one-time scratch).
__device__ unsigned g_cnt[16 * 1024];
__device__ float4 g_WxP[65536];   // 1 MB packed Wx
__device__ float4 g_WhP[65536];   // 1 MB packed Wh

__global__ void zero_cnt() {
    int i = blockIdx.x * blockDim.x + threadIdx.x;
    if (i < 16 * 1024) g_cnt[i] = 0u;
}

// Pack W[k][c] into per-(colgroup, warp, jj, half, lane) float4 = W[k..k+3][c]
// with k = 32w + 4jj, c = 64cg + 32half + l. Consumer loads are fully coalesced
// and give (W[k][c], W[k+1][c]) pairs for the k-in-lanes FMA2 trick.
__global__ void pack_w(const float* __restrict__ Wx,
                       const float* __restrict__ Wh) {
    int i    = blockIdx.x * 256 + threadIdx.x;   // 0..65535
    int l    = i & 31;
    int half = (i >> 5) & 1;
    int jj   = (i >> 6) & 7;
    int w    = (i >> 9) & 15;
    int cg   = i >> 13;
    int k    = w * 32 + jj * 4;
    int c    = cg * 64 + half * 32 + l;
    float4 vx, vh;
    vx.x = Wx[(size_t)(k + 0) * Hn + c];
    vx.y = Wx[(size_t)(k + 1) * Hn + c];
    vx.z = Wx[(size_t)(k + 2) * Hn + c];
    vx.w = Wx[(size_t)(k + 3) * Hn + c];
    vh.x = Wh[(size_t)(k + 0) * Hn + c];
    vh.y = Wh[(size_t)(k + 1) * Hn + c];
    vh.z = Wh[(size_t)(k + 2) * Hn + c];
    vh.w = Wh[(size_t)(k + 3) * Hn + c];
    g_WxP[i] = vx;
    g_WhP[i] = vh;
}

// ---------------------------------------------------------------------------
// Fused persistent RNN: 128 CTAs = 16 rowgroups x 8 colgroups, 512 threads.
// Per step t, CTA (rg,cg) computes for its 8 batch rows x 64 cols:
//   out[t] = tanh( X[:,t,:] @ Wx  +  out[t-1] @ Wh  + bias )
// X-part needs NO peer data -> computed FIRST, hiding the spin-wait for the
// peers' step-(t-1) arrivals. Wh slice in smem; Wx slice L1-resident (LDG);
// X rows warp-uniform 16B LDGs. k-in-lanes FMA2 throughout.
// Sync: producer stcg -> syncthreads -> tid0 fence + atomicAdd(cnt[rg][t]);
// consumer tid0 spins cnt[rg][t-1]==8 (hidden under X-part).
// ---------------------------------------------------------------------------
#define SSTR 520                           // state row stride (floats)
#define SBUF_FLOATS (8 * SSTR)             // 4160
#define PSQ 544                            // partials per k-chunk (8 x 68)
#define PS_FLOATS (16 * PSQ)               // 8704
#define WH_F4 (16 * 8 * 64)                // 8192 float4 = 128 KB
#define RNN_SMEM_BYTES ((SBUF_FLOATS + PS_FLOATS) * 4 + WH_F4 * 16)  // 182528

__global__ __launch_bounds__(512) void rnn_fused(
    const float* __restrict__ X,       // [B, T, H]
    const float* __restrict__ state0,  // [B, H]
    const float* __restrict__ bias,    // [H]
    float* __restrict__ out)           // [T, B, H]
{
    extern __shared__ float sm[];
    float4* Whs = (float4*)sm;                 // [8192] packed Wh slice
    float*  Sbuf = sm + WH_F4 * 4;             // [8][520] state slice
    float*  Ps   = Sbuf + SBUF_FLOATS;         // [16][544] k-chunk partials

    const int tid = threadIdx.x;
    const int w   = tid >> 5;                  // warp = k-chunk [32w, 32w+32)
    const int l   = tid & 31;                  // lane -> cols c0+l, c0+32+l
    const int cg  = blockIdx.x & 7;
    const int rg  = blockIdx.x >> 3;
    const int c0  = cg * 64;
    const int r0  = rg * 8;

    // ---- one-time: packed Wh slice -> smem ----
    {
        const float4* src = g_WhP + (size_t)cg * WH_F4;
#pragma unroll
        for (int i = 0; i < 16; i++)
            Whs[tid + i * 512] = src[tid + i * 512];
    }

    // epilogue mapping: one output element per thread
    const int rr = tid >> 6;                   // 0..7
    const int cc = tid & 63;                   // 0..63
    float* opbase = out + (size_t)(r0 + rr) * Hn + c0 + cc;
    const float bv = bias[c0 + cc];

    // staging mapping: 2 float4 per thread
    const int s_r  = tid >> 7;                 // 0..3 (+4 on second)
    const int s_k4 = (tid & 127) << 2;         // 0..508

    unsigned* cnt = &g_cnt[rg * 1024];
    const float4* wxbase = g_WxP + (size_t)(cg * 16 + w) * (8 * 64);
    const float4* whbase = Whs + (size_t)w * (8 * 64);

    __syncthreads();                           // Whs ready

    for (int t = 0; t < Tn; t++) {
        // ---- X part: no peer dependency, hides the spin below ----
        unsigned long long acc[8][2];
#pragma unroll
        for (int r = 0; r < 8; r++) { acc[r][0] = 0ull; acc[r][1] = 0ull; }

        const float* xb = X + ((size_t)r0 * Tn + t) * Hn + w * 32;
#pragma unroll
        for (int jj = 0; jj < 8; jj++) {
            ulonglong2 wx0 = *(const ulonglong2*)(wxbase + jj * 64 + l);
            ulonglong2 wx1 = *(const ulonglong2*)(wxbase + jj * 64 + 32 + l);
            const float* xk = xb + jj * 4;
#pragma unroll
            for (int r = 0; r < 8; r++) {
                ulonglong2 xv = *(const ulonglong2*)(xk + (size_t)r * (Tn * Hn));
                FMA2(acc[r][0], xv.x, wx0.x);  FMA2(acc[r][0], xv.y, wx0.y);
                FMA2(acc[r][1], xv.x, wx1.x);  FMA2(acc[r][1], xv.y, wx1.y);
            }
        }

        // ---- wait for peers' step t-1 chunks, then stage state ----
        if (t > 0) {
            if (tid == 0) {
                while (*(volatile unsigned*)&cnt[t - 1] < 8u) { }
                __threadfence();               // acquire
            }
            __syncthreads();
        }
        const float* prev = (t == 0) ? state0
                                     : (out + (size_t)(t - 1) * (Bn * Hn));
        {
            float4 v0 = __ldcg((const float4*)(prev + (size_t)(r0 + s_r) * Hn + s_k4));
            float4 v1 = __ldcg((const float4*)(prev + (size_t)(r0 + s_r + 4) * Hn + s_k4));
            *(float4*)(Sbuf + s_r * SSTR + s_k4)       = v0;
            *(float4*)(Sbuf + (s_r + 4) * SSTR + s_k4) = v1;
        }
        __syncthreads();

        // ---- Wh part: state broadcast from smem, packed Wh from smem ----
        const float* sp = Sbuf + w * 32;
#pragma unroll
        for (int jj = 0; jj < 8; jj++) {
            ulonglong2 wh0 = *(const ulonglong2*)(whbase + jj * 64 + l);
            ulonglong2 wh1 = *(const ulonglong2*)(whbase + jj * 64 + 32 + l);
#pragma unroll
            for (int r = 0; r < 8; r++) {
                ulonglong2 sv = *(const ulonglong2*)(sp + r * SSTR + jj * 4);
                FMA2(acc[r][0], sv.x, wh0.x);  FMA2(acc[r][0], sv.y, wh0.y);
                FMA2(acc[r][1], sv.x, wh1.x);  FMA2(acc[r][1], sv.y, wh1.y);
            }
        }

        // ---- partials: cols l and l+32 per row ----
        {
            float* pb = Ps + w * PSQ;
#pragma unroll
            for (int r = 0; r < 8; r++) {
                UF2 u0, u1;
                u0.u = acc[r][0];
                u1.u = acc[r][1];
                pb[r * 68 + l]      = u0.f.x + u0.f.y;
                pb[r * 68 + 32 + l] = u1.f.x + u1.f.y;
            }
        }
        __syncthreads();

        // ---- reduce 16 k-chunks + bias + tanh + publish ----
        {
            const float* pp = Ps + rr * 68 + cc;
            float s = bv;
#pragma unroll
            for (int q = 0; q < 16; q++) s += pp[q * PSQ];
            __stcg(opbase + (size_t)t * (Bn * Hn), tanhf(s));
        }

        if (t != Tn - 1) {
            __syncthreads();                   // all stores issued; Ps/Sbuf safe
            if (tid == 0) {
                __threadfence();               // publish chunk
                atomicAdd(&cnt[t], 1u);        // arrive (no self-spin here)
            }
        }
    }
}

extern "C" void kernel_launch(void* const* d_in, const int* in_sizes, int n_in,
                              void* d_out, int out_size)
{
    const float* X    = (const float*)d_in[0];  // inputs_tensor [B,T,H]
    const float* S0   = (const float*)d_in[1];  // state_tensor  [1,B,H]
    const float* Wx   = (const float*)d_in[2];  // [H,H]
    const float* Wh   = (const float*)d_in[3];  // [H,H]
    const float* bias = (const float*)d_in[4];  // [H]
    float* out = (float*)d_out;                 // [T,B,H]

    (void)in_sizes; (void)n_in; (void)out_size;

    cudaFuncSetAttribute(rnn_fused,
                         cudaFuncAttributeMaxDynamicSharedMemorySize,
                         RNN_SMEM_BYTES);

    zero_cnt<<<32, 512>>>();
    pack_w<<<256, 256>>>(Wx, Wh);
    rnn_fused<<<128, 512, RNN_SMEM_BYTES>>>(X, S0, bias, out);
}

// round 8
// speedup vs baseline: 1.1460x; 1.1460x over previous
#include <cuda_runtime.h>
#include <math.h>
#include <stdint.h>

#define Bn 128
#define Tn 1024
#define Hn 512
#define BnHn (Bn * Hn)

// Packed dual-FMA: acc(f32x2) += a(f32x2) * b(f32x2), IEEE fp32 per lane.
#define FMA2(acc, a, b) \
    asm("fma.rn.f32x2 %0, %1, %2, %0;" : "+l"(acc) : "l"(a), "l"(b))
#define DUP2(d, f) \
    asm("mov.b64 %0, {%1, %1};" : "=l"(d) : "f"(f))

union UF2 { unsigned long long u; float2 f; };

// Flags (zeroed per launch) + packed Wh (rewritten per launch).
__device__ unsigned g_cnt[16 * 1024];       // [rg][t]   RNN step arrivals (target 8)
__device__ unsigned g_cnt_pre[16 * 8 * 8];  // [rg][cg][trange] GEMM arrivals (target 8)
__device__ float4 g_WhP[65536];             // packed Wh, 1 MB

__global__ void zero_cnt() {
    int i = blockIdx.x * blockDim.x + threadIdx.x;
    if (i < 16 * 1024) g_cnt[i] = 0u;
    if (i < 16 * 8 * 8) g_cnt_pre[i] = 0u;
}

// Pack Wh[k][c] so consumer warp-loads are coalesced float4 = Wh[k..k+3][c]:
// index (cg, w(8), jj(16), half(2), lane(32)), k = 64w + 4jj, c = 64cg + 32half + l.
__global__ void pack_wh(const float* __restrict__ Wh) {
    int i    = blockIdx.x * 256 + threadIdx.x;   // 0..65535
    int l    = i & 31;
    int half = (i >> 5) & 1;
    int jj   = (i >> 6) & 15;
    int w    = (i >> 10) & 7;
    int cg   = i >> 13;
    int k    = w * 64 + jj * 4;
    int c    = cg * 64 + half * 32 + l;
    float4 v;
    v.x = Wh[(size_t)(k + 0) * Hn + c];
    v.y = Wh[(size_t)(k + 1) * Hn + c];
    v.z = Wh[(size_t)(k + 2) * Hn + c];
    v.w = Wh[(size_t)(k + 3) * Hn + c];
    g_WhP[i] = v;
}

// ---------------------------------------------------------------------------
// Combined kernel, 256 threads/CTA, grid 8320:
//  bid <  128 : RNN role. CTA (rg,cg) owns 8 batch rows x 64 cols. Persistent
//               over all 1024 steps; per-rowgroup L2 flag sync (as R6).
//               8 warps, warp = k-chunk 64; Wh slice streamed from L1
//               (ldcg is used for ALL other traffic so Wh owns L1).
//  bid >= 128 : GEMM role. Block = (b, trange, cg): writes
//               pre = X@Wx + bias for one b-row, 128 t's, 64 cols into out,
//               then arrives on g_cnt_pre. trange is the slowest grid dim so
//               early timesteps are produced first. Never waits -> deadlock-free.
// RNN waits on g_cnt_pre only at t % 128 == 0.
// ---------------------------------------------------------------------------
#define SSTR 520                            // state row stride (floats)
#define SBUF_FLOATS (8 * SSTR)              // 4160
#define PSQ 544                             // partials per warp (8 rows x 68)
#define PS_FLOATS (8 * PSQ)                 // 4352
#define FUSED_SMEM_BYTES ((SBUF_FLOATS + PS_FLOATS) * 4)   // 34048

__global__ __launch_bounds__(256, 2) void fused(
    const float* __restrict__ X,       // [B, T, H]
    const float* __restrict__ state0,  // [B, H]
    const float* __restrict__ Wx,      // [H, H]
    const float* __restrict__ bias,    // [H]
    float* __restrict__ out)           // [T, B, H]
{
    extern __shared__ float sm[];
    const int bid = blockIdx.x;
    const int tid = threadIdx.x;

    if (bid < 128) {
        // ================= RNN role =================
        float* Sbuf = sm;                       // [8][520] state slice
        float* Ps   = sm + SBUF_FLOATS;         // [8][8][68] warp partials
        const int cg = bid & 7;
        const int rg = bid >> 3;
        const int c0 = cg * 64;
        const int r0 = rg * 8;
        const int w  = tid >> 5;                // warp = k-chunk [64w, 64w+64)
        const int l  = tid & 31;                // lane -> cols c0+l, c0+32+l
        const float4* whbase = g_WhP + ((cg * 8 + w) << 10);
        unsigned* cnt  = &g_cnt[rg * 1024];
        unsigned* cntp = &g_cnt_pre[(rg * 8 + cg) * 8];

        // epilogue: 2 elements per thread (rows rr0 and rr0+4, col cc0)
        const int rr0 = tid >> 6;               // 0..3
        const int cc0 = tid & 63;
        float* opb0 = out + (size_t)(r0 + rr0) * Hn + c0 + cc0;
        float* opb1 = out + (size_t)(r0 + rr0 + 4) * Hn + c0 + cc0;

        for (int t = 0; t < Tn; t++) {
            // ---- wait for peers' step t-1, then stage state ----
            if (t > 0) {
                if (tid == 0) {
                    while (*(volatile unsigned*)&cnt[t - 1] < 8u) { }
                    __threadfence();
                }
                __syncthreads();
            }
            const float* prev = (t == 0) ? state0
                                         : (out + (size_t)(t - 1) * BnHn);
#pragma unroll
            for (int i = 0; i < 4; i++) {
                int idx = tid + i * 256;
                int r   = idx >> 7;
                int k4  = (idx & 127) << 2;
                float4 v = __ldcg((const float4*)(prev + (size_t)(r0 + r) * Hn + k4));
                *(float4*)(Sbuf + r * SSTR + k4) = v;
            }
            __syncthreads();

            // ---- Wh part: 8 rows x 2 cols x k64 per thread ----
            unsigned long long acc[8][2];
#pragma unroll
            for (int r = 0; r < 8; r++) { acc[r][0] = 0ull; acc[r][1] = 0ull; }
            const float* sp = Sbuf + w * 64;
#pragma unroll
            for (int jj = 0; jj < 16; jj++) {
                ulonglong2 wh0 = *(const ulonglong2*)(whbase + jj * 64 + l);
                ulonglong2 wh1 = *(const ulonglong2*)(whbase + jj * 64 + 32 + l);
#pragma unroll
                for (int r = 0; r < 8; r++) {
                    ulonglong2 sv = *(const ulonglong2*)(sp + r * SSTR + jj * 4);
                    FMA2(acc[r][0], sv.x, wh0.x);  FMA2(acc[r][0], sv.y, wh0.y);
                    FMA2(acc[r][1], sv.x, wh1.x);  FMA2(acc[r][1], sv.y, wh1.y);
                }
            }
            {
                float* pb = Ps + w * PSQ;
#pragma unroll
                for (int r = 0; r < 8; r++) {
                    UF2 u0, u1;
                    u0.u = acc[r][0];
                    u1.u = acc[r][1];
                    pb[r * 68 + l]      = u0.f.x + u0.f.y;
                    pb[r * 68 + 32 + l] = u1.f.x + u1.f.y;
                }
            }

            // ---- window gate: pre[t..t+127] must be published by GEMM ----
            if ((t & 127) == 0 && tid == 0) {
                while (*(volatile unsigned*)&cntp[t >> 7] < 8u) { }
                __threadfence();
            }
            __syncthreads();                    // partials ready + gate release

            // ---- reduce 8 warps + pre + tanh + publish values ----
            {
                const float* pp0 = Ps + rr0 * 68 + cc0;
                const float* pp1 = pp0 + 4 * 68;
                float s0 = 0.0f, s1 = 0.0f;
#pragma unroll
                for (int q = 0; q < 8; q++) {
                    s0 += pp0[q * PSQ];
                    s1 += pp1[q * PSQ];
                }
                float* o0 = opb0 + (size_t)t * BnHn;
                float* o1 = opb1 + (size_t)t * BnHn;
                float p0 = __ldcg(o0);
                float p1 = __ldcg(o1);
                __stcg(o0, tanhf(p0 + s0));
                __stcg(o1, tanhf(p1 + s1));
            }

            if (t != Tn - 1) {
                __syncthreads();                // all stores issued
                if (tid == 0) {
                    __threadfence();
                    atomicAdd(&cnt[t], 1u);
                }
            }
        }
    } else {
        // ================= GEMM role =================
        float* As = sm;                         // [16][132]
        float* Bs = sm + 16 * 132;              // [16][68]
        const int g      = bid - 128;
        const int cg     = g & 7;
        const int b      = (g >> 3) & 127;
        const int trange = g >> 10;             // slowest-varying: early t first
        const int bm0 = b * Tn + trange * 128;  // rows m = b*T + t
        const int bn0 = cg * 64;
        const int tr  = (tid >> 4) << 3;
        const int tc  = (tid & 15) << 2;

        unsigned long long acc2[8][2];
#pragma unroll
        for (int i = 0; i < 8; i++) { acc2[i][0] = 0ull; acc2[i][1] = 0ull; }

        for (int k0 = 0; k0 < Hn; k0 += 16) {
#pragma unroll
            for (int v = 0; v < 2; v++) {
                int f   = tid + (v << 8);
                int row = f >> 2;
                int kk  = (f & 3) << 2;
                float4 a = __ldcg((const float4*)(X + (size_t)(bm0 + row) * Hn + k0 + kk));
                As[(kk + 0) * 132 + row] = a.x;
                As[(kk + 1) * 132 + row] = a.y;
                As[(kk + 2) * 132 + row] = a.z;
                As[(kk + 3) * 132 + row] = a.w;
            }
            {
                int kk  = tid >> 4;
                int col = (tid & 15) << 2;
                float4 bvv = __ldcg((const float4*)(Wx + (size_t)(k0 + kk) * Hn + bn0 + col));
                *(float4*)&Bs[kk * 68 + col] = bvv;
            }
            __syncthreads();

#pragma unroll
            for (int kk = 0; kk < 16; kk++) {
                float4 a0 = *(const float4*)&As[kk * 132 + tr];
                float4 a1 = *(const float4*)&As[kk * 132 + tr + 4];
                ulonglong2 bv = *(const ulonglong2*)&Bs[kk * 68 + tc];
                float av[8] = {a0.x, a0.y, a0.z, a0.w, a1.x, a1.y, a1.z, a1.w};
#pragma unroll
                for (int i = 0; i < 8; i++) {
                    unsigned long long d;
                    DUP2(d, av[i]);
                    FMA2(acc2[i][0], d, bv.x);
                    FMA2(acc2[i][1], d, bv.y);
                }
            }
            __syncthreads();
        }

        float4 bb = *(const float4*)(bias + bn0 + tc);
#pragma unroll
        for (int i = 0; i < 8; i++) {
            int m  = bm0 + tr + i;
            int b2 = m >> 10;                   // T = 1024
            int t  = m & 1023;
            UF2 lo, hi;
            lo.u = acc2[i][0];
            hi.u = acc2[i][1];
            float4 o;
            o.x = lo.f.x + bb.x;
            o.y = lo.f.y + bb.y;
            o.z = hi.f.x + bb.z;
            o.w = hi.f.y + bb.w;
            __stcg((float4*)(out + ((size_t)t * Bn + b2) * Hn + bn0 + tc), o);
        }

        __syncthreads();                        // all pre stores issued
        if (tid == 0) {
            __threadfence();
            atomicAdd(&g_cnt_pre[((b >> 3) * 8 + cg) * 8 + trange], 1u);
        }
    }
}

extern "C" void kernel_launch(void* const* d_in, const int* in_sizes, int n_in,
                              void* d_out, int out_size)
{
    const float* X    = (const float*)d_in[0];  // inputs_tensor [B,T,H]
    const float* S0   = (const float*)d_in[1];  // state_tensor  [1,B,H]
    const float* Wx   = (const float*)d_in[2];  // [H,H]
    const float* Wh   = (const float*)d_in[3];  // [H,H]
    const float* bias = (const float*)d_in[4];  // [H]
    float* out = (float*)d_out;                 // [T,B,H]

    (void)in_sizes; (void)n_in; (void)out_size;

    zero_cnt<<<34, 512>>>();
    pack_wh<<<256, 256>>>(Wh);
    fused<<<128 + 8192, 256, FUSED_SMEM_BYTES>>>(X, S0, Wx, bias, out);
}

// round 9
// speedup vs baseline: 1.2849x; 1.1212x over previous
#include <cuda_runtime.h>
#include <math.h>
#include <stdint.h>

#define Bn 128
#define Tn 1024
#define Hn 512

// Packed dual-FMA: acc(f32x2) += a(f32x2) * b(f32x2), IEEE fp32 per lane.
#define FMA2(acc, a, b) \
    asm("fma.rn.f32x2 %0, %1, %2, %0;" : "+l"(acc) : "l"(a), "l"(b))
#define DUP2(d, f) \
    asm("mov.b64 %0, {%1, %1};" : "=l"(d) : "f"(f))
#define PACK2(d, lo, hi) \
    asm("mov.b64 %0, {%1, %2};" : "=l"(d) : "f"(lo), "f"(hi))

union UF2 { unsigned long long u; float2 f; };

// Per-(rowgroup, step) arrival counters. Zeroed by a graph node each launch.
__device__ unsigned g_cnt[16 * 1024];

__global__ void zero_cnt() {
    int i = blockIdx.x * blockDim.x + threadIdx.x;
    if (i < 16 * 1024) g_cnt[i] = 0u;
}

// ---------------------------------------------------------------------------
// Phase 1: pre[t][b][:] = X[b][t][:] @ Wx + bias   (into d_out, [T,B,H])
// BM=128, BN=128, BK=16, 256 threads, 8x8 per thread, fma.rn.f32x2 inner loop.
// Per kk: 4 LDS.128 + 8 DUP + 32 FMA2 for 64 FMA (73% of issue slots are FMA2).
// ---------------------------------------------------------------------------
__global__ __launch_bounds__(256) void gemm_xw(
    const float* __restrict__ X,    // [B*T, H] rows r = b*T + t
    const float* __restrict__ Wx,   // [H, H]
    const float* __restrict__ bias, // [H]
    float* __restrict__ out)        // [T, B, H]
{
    __shared__ float As[16][132];   // [k][row]
    __shared__ float Bs[16][132];   // [k][col]

    const int bm0 = blockIdx.y * 128;
    const int bn0 = blockIdx.x * 128;
    const int tid = threadIdx.x;
    const int tr  = (tid >> 4) << 3;   // row offset 0..120
    const int tc  = (tid & 15) << 3;   // col offset 0..120

    unsigned long long acc2[8][4];
#pragma unroll
    for (int i = 0; i < 8; i++)
#pragma unroll
        for (int j = 0; j < 4; j++) acc2[i][j] = 0ull;

    for (int k0 = 0; k0 < Hn; k0 += 16) {
        // A tile: 128 rows x 16 k = 512 float4; 2 per thread.
#pragma unroll
        for (int v = 0; v < 2; v++) {
            int f   = tid + (v << 8);
            int row = f >> 2;
            int kk  = (f & 3) << 2;
            float4 a = *(const float4*)(X + (size_t)(bm0 + row) * Hn + k0 + kk);
            As[kk + 0][row] = a.x;
            As[kk + 1][row] = a.y;
            As[kk + 2][row] = a.z;
            As[kk + 3][row] = a.w;
        }
        // B tile: 16 k x 128 cols = 512 float4; 2 per thread.
#pragma unroll
        for (int v = 0; v < 2; v++) {
            int f   = tid + (v << 8);
            int kk  = f >> 5;
            int col = (f & 31) << 2;
            *(float4*)&Bs[kk][col] =
                *(const float4*)(Wx + (size_t)(k0 + kk) * Hn + bn0 + col);
        }
        __syncthreads();

#pragma unroll
        for (int kk = 0; kk < 16; kk++) {
            float4 a0 = *(const float4*)&As[kk][tr];
            float4 a1 = *(const float4*)&As[kk][tr + 4];
            ulonglong2 bv0 = *(const ulonglong2*)&Bs[kk][tc];
            ulonglong2 bv1 = *(const ulonglong2*)&Bs[kk][tc + 4];
            float av[8] = {a0.x, a0.y, a0.z, a0.w, a1.x, a1.y, a1.z, a1.w};
#pragma unroll
            for (int i = 0; i < 8; i++) {
                unsigned long long d;
                DUP2(d, av[i]);
                FMA2(acc2[i][0], d, bv0.x);
                FMA2(acc2[i][1], d, bv0.y);
                FMA2(acc2[i][2], d, bv1.x);
                FMA2(acc2[i][3], d, bv1.y);
            }
        }
        __syncthreads();
    }

    float4 bb0 = *(const float4*)(bias + bn0 + tc);
    float4 bb1 = *(const float4*)(bias + bn0 + tc + 4);
#pragma unroll
    for (int i = 0; i < 8; i++) {
        int m = bm0 + tr + i;
        int b = m >> 10;              // T = 1024
        int t = m & 1023;
        UF2 q0, q1, q2, q3;
        q0.u = acc2[i][0];
        q1.u = acc2[i][1];
        q2.u = acc2[i][2];
        q3.u = acc2[i][3];
        float4 o0, o1;
        o0.x = q0.f.x + bb0.x;
        o0.y = q0.f.y + bb0.y;
        o0.z = q1.f.x + bb0.z;
        o0.w = q1.f.y + bb0.w;
        o1.x = q2.f.x + bb1.x;
        o1.y = q2.f.y + bb1.y;
        o1.z = q3.f.x + bb1.z;
        o1.w = q3.f.y + bb1.w;
        float* dst = out + ((size_t)t * Bn + b) * Hn + bn0 + tc;
        *(float4*)(dst)     = o0;
        *(float4*)(dst + 4) = o1;
    }
}

// ---------------------------------------------------------------------------
// Phase 2: ONE persistent kernel (identical to R6's proven 3.4ms version).
// 128 CTAs = 16 rowgroups x 8 colgroups; per-rowgroup L2 flag sync.
// ---------------------------------------------------------------------------
#define SSTR 520                          // state row stride (floats)
#define SBUF_FLOATS (8 * SSTR)            // 4160
#define PSQ 544                           // partials per k-chunk (8 x 68)
#define PS_FLOATS (16 * PSQ)              // 8704
#define RNN_SMEM_BYTES ((SBUF_FLOATS + PS_FLOATS) * 4)   // 51456

__global__ __launch_bounds__(512) void rnn_steps(
    const float* __restrict__ state0,  // [B, H]
    const float* __restrict__ Wh,      // [H, H]
    float* __restrict__ out)           // [T, B, H] (holds pre on entry)
{
    extern __shared__ float sm[];
    float* Sbuf = sm;                     // [8][SSTR] state slice
    float* Ps   = sm + SBUF_FLOATS;       // [16][8][68] k-chunk partials

    const int tid  = threadIdx.x;
    const int w    = tid >> 5;            // warp 0..15 = k-chunk
    const int lane = tid & 31;
    const int cg   = blockIdx.x & 7;
    const int rg   = blockIdx.x >> 3;
    const int c0   = cg * 64;
    const int r0   = rg * 8;

    // weights: thread covers cols {gc, gc+1}, k in [32w, 32w+32)
    const int gc = c0 + lane * 2;
    unsigned long long w2a[16], w2b[16];
    {
        const float* wb = Wh + (size_t)(w * 32) * Hn + gc;
#pragma unroll
        for (int j = 0; j < 16; j++) {
            float a0 = wb[(2 * j) * Hn];
            float a1 = wb[(2 * j + 1) * Hn];
            float b0 = wb[(2 * j) * Hn + 1];
            float b1 = wb[(2 * j + 1) * Hn + 1];
            PACK2(w2a[j], a0, a1);
            PACK2(w2b[j], b0, b1);
        }
    }

    // epilogue mapping: one output element per thread
    const int rr = tid >> 6;              // 0..7
    const int cc = tid & 63;              // 0..63
    float* opbase = out + (size_t)(r0 + rr) * Hn + c0 + cc;

    // staging mapping: 2 float4 per thread
    const int s_r  = tid >> 7;            // 0..3 (+4 on second)
    const int s_k4 = (tid & 127) << 2;    // 0..508

    unsigned* cnt = &g_cnt[rg * 1024];

    for (int t = 0; t < Tn; t++) {
        const float* prev = (t == 0) ? state0
                                     : (out + (size_t)(t - 1) * (Bn * Hn));
        {
            const float4* p0 =
                (const float4*)(prev + (size_t)(r0 + s_r) * Hn + s_k4);
            const float4* p1 =
                (const float4*)(prev + (size_t)(r0 + s_r + 4) * Hn + s_k4);
            float4 v0 = __ldcg(p0);
            float4 v1 = __ldcg(p1);
            *(float4*)(Sbuf + s_r * SSTR + s_k4)       = v0;
            *(float4*)(Sbuf + (s_r + 4) * SSTR + s_k4) = v1;
        }
        __syncthreads();

        float* op = opbase + (size_t)t * (Bn * Hn);
        float pre = __ldcg(op);           // own pre-activation (overlaps compute)

        unsigned long long acc[8][2];
#pragma unroll
        for (int r = 0; r < 8; r++) { acc[r][0] = 0ull; acc[r][1] = 0ull; }

        const float* sp = Sbuf + w * 32;
#pragma unroll
        for (int jj = 0; jj < 8; jj++) {
            const int k = jj * 4;
#pragma unroll
            for (int r = 0; r < 8; r++) {
                ulonglong2 sv = *(const ulonglong2*)(sp + r * SSTR + k);
                FMA2(acc[r][0], sv.x, w2a[2 * jj]);
                FMA2(acc[r][0], sv.y, w2a[2 * jj + 1]);
                FMA2(acc[r][1], sv.x, w2b[2 * jj]);
                FMA2(acc[r][1], sv.y, w2b[2 * jj + 1]);
            }
        }

        {
            float* pb = Ps + w * PSQ + lane * 2;
#pragma unroll
            for (int r = 0; r < 8; r++) {
                UF2 u0, u1;
                u0.u = acc[r][0];
                u1.u = acc[r][1];
                float2 p;
                p.x = u0.f.x + u0.f.y;
                p.y = u1.f.x + u1.f.y;
                *(float2*)(pb + r * 68) = p;
            }
        }
        __syncthreads();

        {
            const float* pp = Ps + rr * 68 + cc;
            float s = 0.0f;
#pragma unroll
            for (int q = 0; q < 16; q++) s += pp[q * PSQ];
            __stcg(op, tanhf(pre + s));
        }

        if (t != Tn - 1) {
            __syncthreads();              // all output stores issued
            if (tid == 0) {
                __threadfence();          // publish chunk before arrive
                atomicAdd(&cnt[t], 1u);
                while (*(volatile unsigned*)&cnt[t] < 8u) { }
                __threadfence();          // acquire
            }
            __syncthreads();              // release whole CTA into t+1
        }
    }
}

extern "C" void kernel_launch(void* const* d_in, const int* in_sizes, int n_in,
                              void* d_out, int out_size)
{
    const float* X    = (const float*)d_in[0];  // inputs_tensor [B,T,H]
    const float* S0   = (const float*)d_in[1];  // state_tensor  [1,B,H]
    const float* Wx   = (const float*)d_in[2];  // [H,H]
    const float* Wh   = (const float*)d_in[3];  // [H,H]
    const float* bias = (const float*)d_in[4];  // [H]
    float* out = (float*)d_out;                 // [T,B,H]

    (void)in_sizes; (void)n_in; (void)out_size;

    cudaFuncSetAttribute(rnn_steps,
                         cudaFuncAttributeMaxDynamicSharedMemorySize,
                         RNN_SMEM_BYTES);

    zero_cnt<<<32, 512>>>();

    dim3 g1(Hn / 128, (Bn * Tn) / 128);  // (4, 1024)
    gemm_xw<<<g1, 256>>>(X, Wx, bias, out);

    rnn_steps<<<128, 512, RNN_SMEM_BYTES>>>(S0, Wh, out);
}

// round 10
// speedup vs baseline: 1.4987x; 1.1664x over previous
#include <cuda_runtime.h>
#include <math.h>
#include <stdint.h>

#define Bn 128
#define Tn 1024
#define Hn 512

// Packed dual-FMA: acc(f32x2) += a(f32x2) * b(f32x2), IEEE fp32 per lane.
#define FMA2(acc, a, b) \
    asm("fma.rn.f32x2 %0, %1, %2, %0;" : "+l"(acc) : "l"(a), "l"(b))
#define DUP2(d, f) \
    asm("mov.b64 %0, {%1, %1};" : "=l"(d) : "f"(f))
#define PACK2(d, lo, hi) \
    asm("mov.b64 %0, {%1, %2};" : "=l"(d) : "f"(lo), "f"(hi))

union UF2 { unsigned long long u; float2 f; };

__device__ unsigned g_cnt[16 * 1024];   // [rg][t] arrivals (target 8)

__global__ void zero_cnt() {
    int i = blockIdx.x * blockDim.x + threadIdx.x;
    if (i < 16 * 1024) g_cnt[i] = 0u;
}

__device__ __forceinline__ unsigned ld_acq(const unsigned* p) {
    unsigned v;
    asm volatile("ld.acquire.gpu.global.u32 %0, [%1];" : "=r"(v) : "l"(p));
    return v;
}

// ---------------------------------------------------------------------------
// Phase 1: pre[t][b][:] = X[b][t][:] @ Wx + bias  (R9's 128x128 tile, proven)
// ---------------------------------------------------------------------------
__global__ __launch_bounds__(256) void gemm_xw(
    const float* __restrict__ X,    // [B*T, H] rows r = b*T + t
    const float* __restrict__ Wx,   // [H, H]
    const float* __restrict__ bias, // [H]
    float* __restrict__ out)        // [T, B, H]
{
    __shared__ float As[16][132];
    __shared__ float Bs[16][132];

    const int bm0 = blockIdx.y * 128;
    const int bn0 = blockIdx.x * 128;
    const int tid = threadIdx.x;
    const int tr  = (tid >> 4) << 3;
    const int tc  = (tid & 15) << 3;

    unsigned long long acc2[8][4];
#pragma unroll
    for (int i = 0; i < 8; i++)
#pragma unroll
        for (int j = 0; j < 4; j++) acc2[i][j] = 0ull;

    for (int k0 = 0; k0 < Hn; k0 += 16) {
#pragma unroll
        for (int v = 0; v < 2; v++) {
            int f   = tid + (v << 8);
            int row = f >> 2;
            int kk  = (f & 3) << 2;
            float4 a = *(const float4*)(X + (size_t)(bm0 + row) * Hn + k0 + kk);
            As[kk + 0][row] = a.x;
            As[kk + 1][row] = a.y;
            As[kk + 2][row] = a.z;
            As[kk + 3][row] = a.w;
        }
#pragma unroll
        for (int v = 0; v < 2; v++) {
            int f   = tid + (v << 8);
            int kk  = f >> 5;
            int col = (f & 31) << 2;
            *(float4*)&Bs[kk][col] =
                *(const float4*)(Wx + (size_t)(k0 + kk) * Hn + bn0 + col);
        }
        __syncthreads();

#pragma unroll
        for (int kk = 0; kk < 16; kk++) {
            float4 a0 = *(const float4*)&As[kk][tr];
            float4 a1 = *(const float4*)&As[kk][tr + 4];
            ulonglong2 bv0 = *(const ulonglong2*)&Bs[kk][tc];
            ulonglong2 bv1 = *(const ulonglong2*)&Bs[kk][tc + 4];
            float av[8] = {a0.x, a0.y, a0.z, a0.w, a1.x, a1.y, a1.z, a1.w};
#pragma unroll
            for (int i = 0; i < 8; i++) {
                unsigned long long d;
                DUP2(d, av[i]);
                FMA2(acc2[i][0], d, bv0.x);
                FMA2(acc2[i][1], d, bv0.y);
                FMA2(acc2[i][2], d, bv1.x);
                FMA2(acc2[i][3], d, bv1.y);
            }
        }
        __syncthreads();
    }

    float4 bb0 = *(const float4*)(bias + bn0 + tc);
    float4 bb1 = *(const float4*)(bias + bn0 + tc + 4);
#pragma unroll
    for (int i = 0; i < 8; i++) {
        int m = bm0 + tr + i;
        int b = m >> 10;
        int t = m & 1023;
        UF2 q0, q1, q2, q3;
        q0.u = acc2[i][0];
        q1.u = acc2[i][1];
        q2.u = acc2[i][2];
        q3.u = acc2[i][3];
        float4 o0, o1;
        o0.x = q0.f.x + bb0.x;
        o0.y = q0.f.y + bb0.y;
        o0.z = q1.f.x + bb0.z;
        o0.w = q1.f.y + bb0.w;
        o1.x = q2.f.x + bb1.x;
        o1.y = q2.f.y + bb1.y;
        o1.z = q3.f.x + bb1.z;
        o1.w = q3.f.y + bb1.w;
        float* dst = out + ((size_t)t * Bn + b) * Hn + bn0 + tc;
        *(float4*)(dst)     = o0;
        *(float4*)(dst + 4) = o1;
    }
}

// ---------------------------------------------------------------------------
// Phase 2: persistent RNN, 128 CTAs = 16 rowgroups x 8 colgroups, 512 thr.
// Per step: all threads acquire-poll cnt[rg][t-1]; each warp self-stages its
// own k-chunk (32 k x 8 rows) via ldcg into its private smem region
// (no CTA staging barrier), FMA2 (weights L1-resident, R6 pattern),
// partials -> sync -> reduce+tanh+stcg -> sync -> tid0 arrive.
// ---------------------------------------------------------------------------
#define SWSTR 36                          // per-warp state row stride (floats)
#define SW_FLOATS (8 * SWSTR)             // 288 per warp
#define PSQ 544                           // partials per k-chunk (8 x 68)
#define RNN_SMEM_BYTES ((16 * SW_FLOATS + 16 * PSQ) * 4)   // 53248

__global__ __launch_bounds__(512) void rnn_steps(
    const float* __restrict__ state0,  // [B, H]
    const float* __restrict__ Wh,      // [H, H]
    float* __restrict__ out)           // [T, B, H] (holds pre on entry)
{
    extern __shared__ float sm[];
    float* SwA = sm;                      // [16][8][36] per-warp state chunks
    float* Ps  = sm + 16 * SW_FLOATS;     // [16][8][68] k-chunk partials

    const int tid  = threadIdx.x;
    const int w    = tid >> 5;            // warp = k-chunk [32w, 32w+32)
    const int lane = tid & 31;
    const int cg   = blockIdx.x & 7;
    const int rg   = blockIdx.x >> 3;
    const int c0   = cg * 64;
    const int r0   = rg * 8;

    // weights: thread covers cols {gc, gc+1}, k in [32w, 32w+32) (R6 pattern)
    const int gc = c0 + lane * 2;
    unsigned long long w2a[16], w2b[16];
    {
        const float* wb = Wh + (size_t)(w * 32) * Hn + gc;
#pragma unroll
        for (int j = 0; j < 16; j++) {
            float a0 = wb[(2 * j) * Hn];
            float a1 = wb[(2 * j + 1) * Hn];
            float b0 = wb[(2 * j) * Hn + 1];
            float b1 = wb[(2 * j + 1) * Hn + 1];
            PACK2(w2a[j], a0, a1);
            PACK2(w2b[j], b0, b1);
        }
    }

    // epilogue mapping: one output element per thread
    const int rr = tid >> 6;              // 0..7
    const int cc = tid & 63;              // 0..63
    float* opbase = out + (size_t)(r0 + rr) * Hn + c0 + cc;

    // self-staging mapping: warp w loads rows 0..7 x k[32w,32w+32)
    const int sr  = lane >> 3;            // 0..3  (and +4 on second load)
    const int sk4 = (lane & 7) << 2;      // 0..28

    float* Sw = SwA + w * SW_FLOATS;
    unsigned* cnt = &g_cnt[rg * 1024];

    for (int t = 0; t < Tn; t++) {
        float* op = opbase + (size_t)t * (Bn * Hn);
        float pre = __ldcg(op);           // pre-activation (written in phase 1)

        // ---- acquire-poll peers' step t-1 (every thread; self-releasing) ----
        if (t > 0) {
            while (ld_acq(&cnt[t - 1]) < 8u) { }
        }

        // ---- self-stage own k-chunk ----
        const float* prev = (t == 0) ? state0
                                     : (out + (size_t)(t - 1) * (Bn * Hn));
        {
            const float* pk = prev + (size_t)r0 * Hn + w * 32 + sk4;
            float4 v0 = __ldcg((const float4*)(pk + (size_t)sr * Hn));
            float4 v1 = __ldcg((const float4*)(pk + (size_t)(sr + 4) * Hn));
            *(float4*)(Sw + sr * SWSTR + sk4)       = v0;
            *(float4*)(Sw + (sr + 4) * SWSTR + sk4) = v1;
        }
        __syncwarp();

        // ---- FMA: 8 rows x 2 cols x 32 k per thread ----
        unsigned long long acc[8][2];
#pragma unroll
        for (int r = 0; r < 8; r++) { acc[r][0] = 0ull; acc[r][1] = 0ull; }
#pragma unroll
        for (int jj = 0; jj < 8; jj++) {
            const int k = jj * 4;
#pragma unroll
            for (int r = 0; r < 8; r++) {
                ulonglong2 sv = *(const ulonglong2*)(Sw + r * SWSTR + k);
                FMA2(acc[r][0], sv.x, w2a[2 * jj]);
                FMA2(acc[r][0], sv.y, w2a[2 * jj + 1]);
                FMA2(acc[r][1], sv.x, w2b[2 * jj]);
                FMA2(acc[r][1], sv.y, w2b[2 * jj + 1]);
            }
        }

        // ---- partials ----
        {
            float* pb = Ps + w * PSQ + lane * 2;
#pragma unroll
            for (int r = 0; r < 8; r++) {
                UF2 u0, u1;
                u0.u = acc[r][0];
                u1.u = acc[r][1];
                float2 p;
                p.x = u0.f.x + u0.f.y;
                p.y = u1.f.x + u1.f.y;
                *(float2*)(pb + r * 68) = p;
            }
        }
        __syncthreads();                  // partials ready

        // ---- reduce 16 k-chunks + tanh + publish value ----
        {
            const float* pp = Ps + rr * 68 + cc;
            float s = 0.0f;
#pragma unroll
            for (int q = 0; q < 16; q++) s += pp[q * PSQ];
            __stcg(op, tanhf(pre + s));
        }
        __syncthreads();                  // stores issued + Ps safe to reuse

        if (t != Tn - 1 && tid == 0) {
            __threadfence();              // publish chunk before arrive
            atomicAdd(&cnt[t], 1u);
        }
    }
}

extern "C" void kernel_launch(void* const* d_in, const int* in_sizes, int n_in,
                              void* d_out, int out_size)
{
    const float* X    = (const float*)d_in[0];  // inputs_tensor [B,T,H]
    const float* S0   = (const float*)d_in[1];  // state_tensor  [1,B,H]
    const float* Wx   = (const float*)d_in[2];  // [H,H]
    const float* Wh   = (const float*)d_in[3];  // [H,H]
    const float* bias = (const float*)d_in[4];  // [H]
    float* out = (float*)d_out;                 // [T,B,H]

    (void)in_sizes; (void)n_in; (void)out_size;

    cudaFuncSetAttribute(rnn_steps,
                         cudaFuncAttributeMaxDynamicSharedMemorySize,
                         RNN_SMEM_BYTES);

    zero_cnt<<<32, 512>>>();

    dim3 g1(Hn / 128, (Bn * Tn) / 128);  // (4, 1024)
    gemm_xw<<<g1, 256>>>(X, Wx, bias, out);

    rnn_steps<<<128, 512, RNN_SMEM_BYTES>>>(S0, Wh, out);
}